// round 8
// baseline (speedup 1.0000x reference)
#include <cuda_runtime.h>
#include <math.h>

#define BN    737280      // total elements (8 * 92160)
#define NPIX  92160       // elements per (b,t) slice
#define NTRK  512
#define NSEG  4096        // 8 * 512
#define NCH   66
#define WCH   68          // padded segment row stride
#define CAP   320         // bucket capacity: mean 179.7, sigma 13.4 -> +10.5 sigma
#define MAXQ  10          // CAP / 32
#define THR   2.0f
#define DKS   0.05f

// ---------------- scratch (device globals; no allocation) ----------------
__device__ int                        g_cnt[NSEG];
__device__ int                        g_order[NSEG * CAP];     // 5.24 MB
__device__ __align__(16) float        g_srow[NSEG * WCH];      // finalized segment row
__device__ int                        g_rep[NSEG];
__device__ unsigned char              g_flags[BN];

// ordered-uint mapping for floats (bijective, order-preserving)
__device__ __forceinline__ unsigned fok(float f) {
    unsigned b = __float_as_uint(f);
    return (b & 0x80000000u) ? ~b : (b | 0x80000000u);
}
__device__ __forceinline__ float kof(unsigned u) {
    unsigned b = (u & 0x80000000u) ? (u & 0x7FFFFFFFu) : ~u;
    return __uint_as_float(b);
}

// load all 66 channels for element i into buf (k3 passthrough path)
// order: center(0-2) offset(3-5) opacity(6) scale(7-9) rotation(10-13)
//        feat_dc(14-16) keep(17) inst(18-49) motion(50-65)
__device__ __forceinline__ void load_row(
    int i, float* buf,
    const float* __restrict__ cen, const float* __restrict__ off,
    const float* __restrict__ opa, const float* __restrict__ sca,
    const float* __restrict__ rot, const float* __restrict__ fdc,
    const float* __restrict__ kp,  const float* __restrict__ ins,
    const float* __restrict__ mot) {
    #pragma unroll
    for (int c = 0; c < 3; c++) buf[c]      = cen[3 * i + c];
    #pragma unroll
    for (int c = 0; c < 3; c++) buf[3 + c]  = off[3 * i + c];
    buf[6] = opa[i];
    #pragma unroll
    for (int c = 0; c < 3; c++) buf[7 + c]  = sca[3 * i + c];
    {
        float4 r4 = reinterpret_cast<const float4*>(rot)[i];
        buf[10] = r4.x; buf[11] = r4.y; buf[12] = r4.z; buf[13] = r4.w;
    }
    #pragma unroll
    for (int c = 0; c < 3; c++) buf[14 + c] = fdc[3 * i + c];
    buf[17] = kp[i];
    const float4* ip = reinterpret_cast<const float4*>(ins) + (size_t)i * 8;
    #pragma unroll
    for (int q = 0; q < 8; q++) {
        float4 v = ip[q];
        buf[18 + 4 * q + 0] = v.x; buf[18 + 4 * q + 1] = v.y;
        buf[18 + 4 * q + 2] = v.z; buf[18 + 4 * q + 3] = v.w;
    }
    const float4* mp = reinterpret_cast<const float4*>(mot) + (size_t)i * 4;
    #pragma unroll
    for (int q = 0; q < 4; q++) {
        float4 v = mp[q];
        buf[50 + 4 * q + 0] = v.x; buf[50 + 4 * q + 1] = v.y;
        buf[50 + 4 * q + 2] = v.z; buf[50 + 4 * q + 3] = v.w;
    }
}

// ---------------- kernels ----------------
// bucket valid elements by segment
__global__ void __launch_bounds__(256)
k_bucket(const int* __restrict__ gid) {
    int i = blockIdx.x * blockDim.x + threadIdx.x;
    if (i >= BN) return;
    int g = gid[i];
    if (g < 0) return;
    int s = (i / NPIX) * NTRK + g;
    int pos = atomicAdd(&g_cnt[s], 1);
    if (pos < CAP) g_order[s * CAP + pos] = i;
}

// warp-per-segment: phase-1 softmax mean, activity, cooperative weighted
// accumulation (lanes own channels), rep/m2, finalize segment row. No atomics.
__global__ void __launch_bounds__(256)
k_acc(const float* __restrict__ cen, const float* __restrict__ off,
      const float* __restrict__ opa, const float* __restrict__ sca,
      const float* __restrict__ rot, const float* __restrict__ fdc,
      const float* __restrict__ kp,  const float* __restrict__ ins,
      const float* __restrict__ mot) {
    const unsigned FULL = 0xFFFFFFFFu;
    int w    = (blockIdx.x * blockDim.x + threadIdx.x) >> 5;
    int lane = threadIdx.x & 31;
    if (w >= NSEG) return;
    int s  = w;
    int n0 = g_cnt[s];
    if (n0 < 2) return;                 // not dup: flags stay 0 -> passthrough
    int n = n0 < CAP ? n0 : CAP;

    // ---- phase 1: z1 and weighted center mean over ALL n elements ----
    int   idxv[MAXQ];
    float kpv[MAXQ];
    float z1 = 0.f, wx = 0.f, wy = 0.f, wz = 0.f;
    #pragma unroll
    for (int q = 0; q < MAXQ; q++) {
        int p = lane + q * 32;
        bool v = p < n;
        int i = v ? g_order[s * CAP + p] : 0;
        idxv[q] = i;
        float k0 = v ? __ldg(kp + i) : 0.f;
        kpv[q] = k0;
        if (v) {
            float e = __expf(k0);
            z1 += e;
            wx += e * cen[3 * i + 0];
            wy += e * cen[3 * i + 1];
            wz += e * cen[3 * i + 2];
        }
    }
    #pragma unroll
    for (int o = 16; o > 0; o >>= 1) {
        z1 += __shfl_xor_sync(FULL, z1, o);
        wx += __shfl_xor_sync(FULL, wx, o);
        wy += __shfl_xor_sync(FULL, wy, o);
        wz += __shfl_xor_sync(FULL, wz, o);
    }
    float zi1 = 1.f / fmaxf(z1, 1e-20f);
    float mx = wx * zi1, my = wy * zi1, mz = wz * zi1;

    // ---- phase 1.5: activity, z2, representative key, flags ----
    unsigned amask = 0;
    float z2 = 0.f;
    unsigned long long key = 0xFFFFFFFFFFFFFFFFull;
    #pragma unroll
    for (int q = 0; q < MAXQ; q++) {
        int p = lane + q * 32;
        if (p < n) {
            int i = idxv[q];
            float dx = cen[3 * i + 0] - mx;
            float dy = cen[3 * i + 1] - my;
            float dz = cen[3 * i + 2] - mz;
            if (sqrtf(dx * dx + dy * dy + dz * dz) <= THR) {
                amask |= 1u << q;
                z2 += __expf(kpv[q]);
                unsigned long long k =
                    ((unsigned long long)(~fok(kpv[q])) << 32) | (unsigned)i;
                if (k < key) key = k;
                g_flags[i] = 1;
            }
        }
    }
    #pragma unroll
    for (int o = 16; o > 0; o >>= 1) {
        z2 += __shfl_xor_sync(FULL, z2, o);
        unsigned long long ok = __shfl_xor_sync(FULL, key, o);
        if (ok < key) key = ok;
    }
    if (z2 == 0.f) return;   // no active elements; nothing reads srow[s]

    // ---- per-lane (base, stride): channel group 0 = lane, 1 = lane+32, 2 = 64+lane ----
    const float* A0; int S0;
    if      (lane <  3) { A0 = cen + lane;       S0 = 3;  }
    else if (lane <  6) { A0 = off + lane - 3;   S0 = 3;  }
    else if (lane <  7) { A0 = opa;              S0 = 1;  }
    else if (lane < 10) { A0 = sca + lane - 7;   S0 = 3;  }
    else if (lane < 14) { A0 = rot + lane - 10;  S0 = 4;  }
    else if (lane < 17) { A0 = fdc + lane - 14;  S0 = 3;  }
    else if (lane < 18) { A0 = kp;               S0 = 1;  }
    else                { A0 = ins + lane - 18;  S0 = 32; }
    const float* A1; int S1;
    if (lane < 18) { A1 = ins + 14 + lane; S1 = 32; }
    else           { A1 = mot + lane - 18; S1 = 16; }
    const float* A2 = mot + 14 + (lane & 1);        // lanes 0,1 only

    // ---- phase 2: cooperative accumulation, lanes own channels ----
    float acc0 = 0.f, acc1 = 0.f, acc2 = 0.f;
    #pragma unroll
    for (int q = 0; q < MAXQ; q++) {
        if (q * 32 >= n) break;
        int m = n - q * 32; if (m > 32) m = 32;
        for (int po = 0; po < m; po++) {
            unsigned am = __shfl_sync(FULL, amask, po);
            if ((am >> q) & 1u) {
                int   i   = __shfl_sync(FULL, idxv[q], po);
                float k0b = __shfl_sync(FULL, kpv[q],  po);
                float e   = __expf(k0b);
                acc0 += e * __ldg(A0 + (size_t)i * S0);
                acc1 += e * __ldg(A1 + (size_t)i * S1);
                if (lane < 2) acc2 += e * __ldg(A2 + (size_t)i * 16);
            }
        }
    }

    // ---- finalize ----
    float zi2 = 1.f / z2;
    acc0 *= zi2; acc1 *= zi2; acc2 *= zi2;

    // rotation channels 10..13 live in group 0
    float r10 = __shfl_sync(FULL, acc0, 10);
    float r11 = __shfl_sync(FULL, acc0, 11);
    float r12 = __shfl_sync(FULL, acc0, 12);
    float r13 = __shfl_sync(FULL, acc0, 13);
    float nr  = sqrtf(r10 * r10 + r11 * r11 + r12 * r12 + r13 * r13);
    float ri  = 1.f / fmaxf(nr, 1e-12f);
    if (lane >= 10 && lane <= 13) acc0 *= ri;

    float m2 = kof(~(unsigned)(key >> 32));
    if (lane == 17) acc0 = m2;          // mkeep = segment max keep over active

    float* r = &g_srow[(size_t)s * WCH];
    r[lane]      = acc0;
    r[lane + 32] = acc1;
    if (lane < 2) r[lane + 64] = acc2;
    if (lane == 0) g_rep[s] = (int)(unsigned)(key & 0xFFFFFFFFull);
}

// output: gather (segment row for active, raw channels for inactive),
// stage in smem, write fully coalesced
__global__ void __launch_bounds__(128)
k3(const float* __restrict__ cen, const float* __restrict__ off,
   const float* __restrict__ opa, const float* __restrict__ sca,
   const float* __restrict__ rot, const float* __restrict__ fdc,
   const float* __restrict__ kp,  const float* __restrict__ ins,
   const float* __restrict__ mot, const int* __restrict__ gid,
   float* __restrict__ out) {
    __shared__ float stage[128 * NCH];   // 33,792 B
    int tid = threadIdx.x;
    int i = blockIdx.x * 128 + tid;

    float buf[NCH];
    if (g_flags[i]) {
        int s = (i / NPIX) * NTRK + gid[i];
        const float* r = &g_srow[(size_t)s * WCH];
        #pragma unroll
        for (int c = 0; c < NCH; c++) buf[c] = r[c];
        float sfac = (i == g_rep[s]) ? 1.0f : DKS;
        buf[6]  *= sfac;
        buf[17] *= sfac;
    } else {
        load_row(i, buf, cen, off, opa, sca, rot, fdc, kp, ins, mot);
    }
    #pragma unroll
    for (int c = 0; c < NCH; c++) stage[tid * NCH + c] = buf[c];
    __syncthreads();

    float4* dst = reinterpret_cast<float4*>(out + (size_t)blockIdx.x * 128 * NCH);
    const float4* src = reinterpret_cast<const float4*>(stage);
    for (int idx = tid; idx < (128 * NCH) / 4; idx += 128)
        dst[idx] = src[idx];
}

// ---------------- launcher ----------------
extern "C" void kernel_launch(void* const* d_in, const int* in_sizes, int n_in,
                              void* d_out, int out_size) {
    const float* cen = (const float*)d_in[0];
    const float* off = (const float*)d_in[1];
    const float* opa = (const float*)d_in[2];
    const float* sca = (const float*)d_in[3];
    const float* rot = (const float*)d_in[4];
    const float* fdc = (const float*)d_in[5];
    const float* kp  = (const float*)d_in[6];
    const float* ins = (const float*)d_in[7];
    const float* mot = (const float*)d_in[8];
    const int*   gid = (const int*)d_in[9];
    float* out = (float*)d_out;

    void *p_cnt, *p_flags;
    cudaGetSymbolAddress(&p_cnt,   g_cnt);
    cudaGetSymbolAddress(&p_flags, g_flags);
    cudaMemsetAsync(p_cnt,   0, (size_t)NSEG * sizeof(int));
    cudaMemsetAsync(p_flags, 0, (size_t)BN);

    const int TB = 256;
    k_bucket<<<(BN + TB - 1) / TB, TB>>>(gid);
    k_acc   <<<(NSEG * 32) / TB, TB>>>(cen, off, opa, sca, rot, fdc, kp, ins, mot);
    k3      <<<BN / 128, 128>>>(cen, off, opa, sca, rot, fdc, kp, ins, mot, gid, out);
}

// round 9
// speedup vs baseline: 1.3284x; 1.3284x over previous
#include <cuda_runtime.h>
#include <math.h>

#define BN    737280      // total elements (8 * 92160)
#define NPIX  92160       // elements per (b,t) slice
#define NTRK  512
#define NSEG  4096        // 8 * 512
#define NCH   66
#define WCH   68          // padded accumulator row (16B-aligned stride)
#define REPL  4           // accumulator replicas (contention spreading)
#define THR   2.0f
#define DKS   0.05f

// ---------------- scratch (device globals; no allocation) ----------------
__device__ int                        g_cnt[REPL * NSEG];
__device__ __align__(16) float4       g_p1[REPL * NSEG];          // {z1, wx, wy, wz}
__device__ unsigned long long         g_repkey[REPL * NSEG];      // (~fok(k0))<<32 | idx
__device__ __align__(16) float        g_wsum[REPL * NSEG * WCH];  // [0..65]=w*ch, [66]=z2
__device__ __align__(16) float        g_srow[NSEG * WCH];         // finalized segment row
__device__ int                        g_rep[NSEG];
__device__ unsigned char              g_flags[BN];

// ordered-uint mapping for floats (bijective, order-preserving)
__device__ __forceinline__ unsigned fok(float f) {
    unsigned b = __float_as_uint(f);
    return (b & 0x80000000u) ? ~b : (b | 0x80000000u);
}
__device__ __forceinline__ float kof(unsigned u) {
    unsigned b = (u & 0x80000000u) ? (u & 0x7FFFFFFFu) : ~u;
    return __uint_as_float(b);
}
__device__ __forceinline__ int seg_of(int i, int g) {
    return (i / NPIX) * NTRK + g;
}
__device__ __forceinline__ void red_add_v4(float* p, float a, float b, float c, float d) {
    asm volatile("red.global.add.v4.f32 [%0], {%1, %2, %3, %4};"
                 :: "l"(p), "f"(a), "f"(b), "f"(c), "f"(d) : "memory");
}

// load all 66 channels for element i into buf
// order: center(0-2) offset(3-5) opacity(6) scale(7-9) rotation(10-13)
//        feat_dc(14-16) keep(17) inst(18-49) motion(50-65)
__device__ __forceinline__ void load_row(
    int i, float* buf,
    const float* __restrict__ cen, const float* __restrict__ off,
    const float* __restrict__ opa, const float* __restrict__ sca,
    const float* __restrict__ rot, const float* __restrict__ fdc,
    const float* __restrict__ kp,  const float* __restrict__ ins,
    const float* __restrict__ mot) {
    #pragma unroll
    for (int c = 0; c < 3; c++) buf[c]      = cen[3 * i + c];
    #pragma unroll
    for (int c = 0; c < 3; c++) buf[3 + c]  = off[3 * i + c];
    buf[6] = opa[i];
    #pragma unroll
    for (int c = 0; c < 3; c++) buf[7 + c]  = sca[3 * i + c];
    {
        float4 r4 = reinterpret_cast<const float4*>(rot)[i];
        buf[10] = r4.x; buf[11] = r4.y; buf[12] = r4.z; buf[13] = r4.w;
    }
    #pragma unroll
    for (int c = 0; c < 3; c++) buf[14 + c] = fdc[3 * i + c];
    buf[17] = kp[i];
    const float4* ip = reinterpret_cast<const float4*>(ins) + (size_t)i * 8;
    #pragma unroll
    for (int q = 0; q < 8; q++) {
        float4 v = ip[q];
        buf[18 + 4 * q + 0] = v.x; buf[18 + 4 * q + 1] = v.y;
        buf[18 + 4 * q + 2] = v.z; buf[18 + 4 * q + 3] = v.w;
    }
    const float4* mp = reinterpret_cast<const float4*>(mot) + (size_t)i * 4;
    #pragma unroll
    for (int q = 0; q < 4; q++) {
        float4 v = mp[q];
        buf[50 + 4 * q + 0] = v.x; buf[50 + 4 * q + 1] = v.y;
        buf[50 + 4 * q + 2] = v.z; buf[50 + 4 * q + 3] = v.w;
    }
}

// ---------------- kernels ----------------
// count + phase-1 softmax sums into per-replica accumulators
__global__ void k1(const float* __restrict__ cen, const float* __restrict__ kp,
                   const int* __restrict__ gid) {
    int i = blockIdx.x * blockDim.x + threadIdx.x;
    if (i >= BN) return;
    int g = gid[i];
    if (g < 0) return;
    int s = seg_of(i, g) + (blockIdx.x & (REPL - 1)) * NSEG;
    atomicAdd(&g_cnt[s], 1);
    float e = __expf(kp[i]);
    red_add_v4(&g_p1[s].x, e, e * cen[3 * i + 0], e * cen[3 * i + 1], e * cen[3 * i + 2]);
}

// collapse phase-1 replicas into replica 0
__global__ void k_p1red() {
    int s = blockIdx.x * blockDim.x + threadIdx.x;
    if (s >= NSEG) return;
    int cnt = 0;
    float4 acc = make_float4(0.f, 0.f, 0.f, 0.f);
    #pragma unroll
    for (int r = 0; r < REPL; r++) {
        cnt += g_cnt[r * NSEG + s];
        float4 p = g_p1[r * NSEG + s];
        acc.x += p.x; acc.y += p.y; acc.z += p.z; acc.w += p.w;
    }
    g_cnt[s] = cnt;
    g_p1[s]  = acc;
}

// activity + weighted accumulation (per-replica) + representative key
__global__ void __launch_bounds__(256)
k2(const float* __restrict__ cen, const float* __restrict__ off,
   const float* __restrict__ opa, const float* __restrict__ sca,
   const float* __restrict__ rot, const float* __restrict__ fdc,
   const float* __restrict__ kp,  const float* __restrict__ ins,
   const float* __restrict__ mot, const int* __restrict__ gid) {
    int i = blockIdx.x * blockDim.x + threadIdx.x;
    if (i >= BN) return;
    int g = gid[i];
    int s = 0;
    unsigned char f = 0;
    float k0 = 0.0f;
    if (g >= 0) {
        s = seg_of(i, g);
        if (g_cnt[s] >= 2) {
            float4 p = g_p1[s];
            float zinv = 1.0f / fmaxf(p.x, 1e-20f);
            float dx = cen[3 * i + 0] - p.y * zinv;
            float dy = cen[3 * i + 1] - p.z * zinv;
            float dz = cen[3 * i + 2] - p.w * zinv;
            if (sqrtf(dx * dx + dy * dy + dz * dz) <= THR) {
                f = 1;
                k0 = kp[i];
            }
        }
    }
    g_flags[i] = f;
    if (!f) return;

    float buf[NCH];
    load_row(i, buf, cen, off, opa, sca, rot, fdc, kp, ins, mot);
    float e = __expf(k0);
    int sr = s + (blockIdx.x & (REPL - 1)) * NSEG;
    float* ws = &g_wsum[(size_t)sr * WCH];
    #pragma unroll
    for (int q = 0; q < 16; q++)
        red_add_v4(ws + 4 * q,
                   e * buf[4 * q + 0], e * buf[4 * q + 1],
                   e * buf[4 * q + 2], e * buf[4 * q + 3]);
    red_add_v4(ws + 64, e * buf[64], e * buf[65], e, 0.0f);

    unsigned long long key =
        ((unsigned long long)(~fok(k0)) << 32) | (unsigned)i;
    atomicMin(&g_repkey[sr], key);
}

// warp-per-segment finalize: collapse replicas, means, rotation norm, mkeep, rep
__global__ void __launch_bounds__(256)
k_seg() {
    const unsigned FULL = 0xFFFFFFFFu;
    int warp = (blockIdx.x * blockDim.x + threadIdx.x) >> 5;
    int lane = threadIdx.x & 31;
    if (warp >= NSEG) return;
    int s = warp;

    // lane c owns channels c, c+32, c+64 (coalesced across the warp)
    float a0 = 0.f, a1 = 0.f, a2 = 0.f;
    #pragma unroll
    for (int r = 0; r < REPL; r++) {
        const float* ws = &g_wsum[(size_t)(r * NSEG + s) * WCH];
        a0 += ws[lane];
        a1 += ws[lane + 32];
        if (lane < 4) a2 += ws[lane + 64];
    }
    // z2 lives at channel 66 -> lane 2 of the third group
    float z2   = __shfl_sync(FULL, a2, 2);
    float zinv = 1.0f / fmaxf(z2, 1e-20f);
    a0 *= zinv; a1 *= zinv; a2 *= zinv;

    // rotation channels 10..13 (group 0)
    float r10 = __shfl_sync(FULL, a0, 10);
    float r11 = __shfl_sync(FULL, a0, 11);
    float r12 = __shfl_sync(FULL, a0, 12);
    float r13 = __shfl_sync(FULL, a0, 13);
    float nr  = sqrtf(r10 * r10 + r11 * r11 + r12 * r12 + r13 * r13);
    float ri  = 1.0f / fmaxf(nr, 1e-12f);
    if (lane >= 10 && lane <= 13) a0 *= ri;

    // representative key: min over replicas (lane 0), broadcast
    unsigned long long key = 0xFFFFFFFFFFFFFFFFull;
    if (lane == 0) {
        #pragma unroll
        for (int r = 0; r < REPL; r++) {
            unsigned long long k = g_repkey[r * NSEG + s];
            if (k < key) key = k;
        }
        g_rep[s] = (int)(unsigned)(key & 0xFFFFFFFFull);
    }
    key = __shfl_sync(FULL, key, 0);
    float m2 = kof(~(unsigned)(key >> 32));
    if (lane == 17) a0 = m2;   // mkeep = segment max keep over active

    float* r = &g_srow[(size_t)s * WCH];
    r[lane]      = a0;
    r[lane + 32] = a1;
    if (lane < 2) r[lane + 64] = a2;   // channels 64, 65
}

// output: gather (segment row for active, raw channels for inactive),
// stage in smem, write fully coalesced. srow gather is float4-vectorized
// to cut L1TEX wavefronts ~4x (each row is 16B-aligned, stride 272B).
__global__ void __launch_bounds__(128)
k3(const float* __restrict__ cen, const float* __restrict__ off,
   const float* __restrict__ opa, const float* __restrict__ sca,
   const float* __restrict__ rot, const float* __restrict__ fdc,
   const float* __restrict__ kp,  const float* __restrict__ ins,
   const float* __restrict__ mot, const int* __restrict__ gid,
   float* __restrict__ out) {
    __shared__ float stage[128 * NCH];   // 33,792 B
    int tid = threadIdx.x;
    int i = blockIdx.x * 128 + tid;

    float buf[NCH];
    if (g_flags[i]) {
        int s = seg_of(i, gid[i]);
        const float4* r4 = reinterpret_cast<const float4*>(&g_srow[(size_t)s * WCH]);
        #pragma unroll
        for (int q = 0; q < 16; q++) {
            float4 v = __ldg(r4 + q);
            buf[4 * q + 0] = v.x; buf[4 * q + 1] = v.y;
            buf[4 * q + 2] = v.z; buf[4 * q + 3] = v.w;
        }
        {
            float4 v = __ldg(r4 + 16);   // channels 64,65 (+ z2, pad)
            buf[64] = v.x; buf[65] = v.y;
        }
        float sfac = (i == g_rep[s]) ? 1.0f : DKS;
        buf[6]  *= sfac;
        buf[17] *= sfac;
    } else {
        load_row(i, buf, cen, off, opa, sca, rot, fdc, kp, ins, mot);
    }
    #pragma unroll
    for (int c = 0; c < NCH; c++) stage[tid * NCH + c] = buf[c];
    __syncthreads();

    float4* dst = reinterpret_cast<float4*>(out + (size_t)blockIdx.x * 128 * NCH);
    const float4* src = reinterpret_cast<const float4*>(stage);
    for (int idx = tid; idx < (128 * NCH) / 4; idx += 128)
        dst[idx] = src[idx];
}

// ---------------- launcher ----------------
extern "C" void kernel_launch(void* const* d_in, const int* in_sizes, int n_in,
                              void* d_out, int out_size) {
    const float* cen = (const float*)d_in[0];
    const float* off = (const float*)d_in[1];
    const float* opa = (const float*)d_in[2];
    const float* sca = (const float*)d_in[3];
    const float* rot = (const float*)d_in[4];
    const float* fdc = (const float*)d_in[5];
    const float* kp  = (const float*)d_in[6];
    const float* ins = (const float*)d_in[7];
    const float* mot = (const float*)d_in[8];
    const int*   gid = (const int*)d_in[9];
    float* out = (float*)d_out;

    // zero/initialize scratch via memset nodes (graph-capturable, no alloc)
    void *p_cnt, *p_p1, *p_key, *p_wsum;
    cudaGetSymbolAddress(&p_cnt,  g_cnt);
    cudaGetSymbolAddress(&p_p1,   g_p1);
    cudaGetSymbolAddress(&p_key,  g_repkey);
    cudaGetSymbolAddress(&p_wsum, g_wsum);
    cudaMemsetAsync(p_cnt,  0,    (size_t)REPL * NSEG * sizeof(int));
    cudaMemsetAsync(p_p1,   0,    (size_t)REPL * NSEG * sizeof(float4));
    cudaMemsetAsync(p_key,  0xFF, (size_t)REPL * NSEG * sizeof(unsigned long long));
    cudaMemsetAsync(p_wsum, 0,    (size_t)REPL * NSEG * WCH * sizeof(float));

    const int TB = 256;
    const int GB = (BN + TB - 1) / TB;   // 2880

    k1     <<<GB, TB>>>(cen, kp, gid);
    k_p1red<<<NSEG / TB, TB>>>();
    k2     <<<GB, TB>>>(cen, off, opa, sca, rot, fdc, kp, ins, mot, gid);
    k_seg  <<<(NSEG * 32) / TB, TB>>>();
    k3     <<<BN / 128, 128>>>(cen, off, opa, sca, rot, fdc, kp, ins, mot, gid, out);
}